// round 2
// baseline (speedup 1.0000x reference)
#include <cuda_runtime.h>
#include <cuda_bf16.h>
#include <mma.h>

using namespace nvcuda;

// Problem dims (fixed by reference): B=32, L=512, D=256, H=4
#define BB 32
#define LL 512
#define DD 256
#define HH 4
#define NTOK (BB * LL)            // 16384
#define BH (BB * HH)              // 128
#define HD (HH * DD)              // 1024

// ---------------- device scratch (allocation-free; .bss) ----------------
__device__ __align__(256) float g_Qp[NTOK * DD];
__device__ __align__(256) float g_Kp[NTOK * DD];
__device__ __align__(256) float g_Vp[NTOK * DD];
__device__ __align__(256) float g_Qh[BH * LL * DD];
__device__ __align__(256) float g_Kh[BH * LL * DD];
__device__ __align__(256) float g_Vh[BH * LL * DD];
__device__ __align__(256) float g_S[(size_t)BH * LL * LL];   // scores / probs (in-place)
__device__ __align__(256) float g_Vm[NTOK * HD];             // merged heads (B,L,H*D)
__device__ __align__(256) float g_T1[NTOK * DD];             // attn out-proj
__device__ __align__(256) float g_X[NTOK * DD];              // LN1 output
__device__ __align__(256) float g_Y[NTOK * DD];              // FFN hidden
__device__ __align__(256) float g_Z[NTOK * DD];              // FFN out
__device__ int g_pad[NTOK];
__device__ int g_byte_mode;

// ---------------- mask dtype sniffing + decode ----------------
// If mask stored as 1-byte bools: bytes at offsets 4i+1 are ~50% nonzero.
// If stored as int32 (0/1) or float32 (0.0/1.0): bytes at offsets 4i+1 are all zero.
__global__ void detect_mask_kernel(const unsigned char* m) {
    __shared__ int any;
    if (threadIdx.x == 0) any = 0;
    __syncthreads();
    int local = 0;
    for (int i = threadIdx.x; i < NTOK / 4; i += blockDim.x)
        if (m[4 * i + 1]) local = 1;
    if (local) atomicOr(&any, 1);
    __syncthreads();
    if (threadIdx.x == 0) g_byte_mode = any;
}

__global__ void decode_mask_kernel(const void* m) {
    int i = blockIdx.x * blockDim.x + threadIdx.x;
    if (i >= NTOK) return;
    int v;
    if (g_byte_mode)
        v = ((const unsigned char*)m)[i] != 0;
    else
        v = ((const int*)m)[i] != 0;   // covers int32 0/1 AND float32 0.0/1.0 bit patterns
    g_pad[i] = v;
}

// ---------------- positional encoding add ----------------
__global__ void add_pe_kernel(const float* __restrict__ in, const float* __restrict__ pe,
                              float* __restrict__ out) {
    int i = blockIdx.x * blockDim.x + threadIdx.x;
    if (i >= NTOK * DD) return;
    int d = i & (DD - 1);
    int l = (i >> 8) & (LL - 1);
    out[i] = in[i] + pe[l * DD + d];
}

// ---------------- generic tf32 wmma GEMM ----------------
// C = alpha * A @ op(B) (+bias) (+relu), output scatter per `mode`.
// Tiles: BM=64, BN=64, BK=32; 4 warps (2x2), each warp 32x32 via 2x2 m16n16k8 frags.
// All M,N multiples of 64 and K multiples of 32 in this problem -> no bounds checks.
#define GBM 64
#define GBN 64
#define GBK 32
#define AS_LD 36
#define BS_LD 68
#define CS_LD 68

#define MODE_PLAIN 0
#define MODE_HEADSPLIT 1
#define MODE_MERGE 2

template <bool TRANSB>
__global__ void __launch_bounds__(128)
gemm_tf32(const float* __restrict__ A, const float* __restrict__ B,
          float* __restrict__ C, int M, int N, int K,
          long long aBatch, long long bBatch, long long cBatch,
          int mode, const float* __restrict__ bias, float alpha, int doRelu) {
    __shared__ float sbuf[4480];
    float* As = sbuf;                 // [64][36]
    float* Bs = sbuf + GBM * AS_LD;   // [32][68]

    const int bz = blockIdx.z;
    const float* Ab = A + (long long)bz * aBatch;
    const float* Bb = B + (long long)bz * bBatch;
    const int bm0 = blockIdx.y * GBM;
    const int bn0 = blockIdx.x * GBN;
    const int tid = threadIdx.x;
    const int warp = tid >> 5;
    const int wr = warp >> 1, wc = warp & 1;

    wmma::fragment<wmma::accumulator, 16, 16, 8, float> acc[2][2];
#pragma unroll
    for (int i = 0; i < 2; i++)
#pragma unroll
        for (int j = 0; j < 2; j++) wmma::fill_fragment(acc[i][j], 0.0f);

    for (int k0 = 0; k0 < K; k0 += GBK) {
        // stage A (row-major M x K): 64x32 floats, float4 per thread
#pragma unroll
        for (int l = tid * 4; l < GBM * GBK; l += 128 * 4) {
            int r = l >> 5, c = l & 31;
            float4 v = *(const float4*)(Ab + (long long)(bm0 + r) * K + k0 + c);
            As[r * AS_LD + c + 0] = wmma::__float_to_tf32(v.x);
            As[r * AS_LD + c + 1] = wmma::__float_to_tf32(v.y);
            As[r * AS_LD + c + 2] = wmma::__float_to_tf32(v.z);
            As[r * AS_LD + c + 3] = wmma::__float_to_tf32(v.w);
        }
        // stage B into k-major Bs[k][n]
        if (!TRANSB) {
            // B row-major K x N
#pragma unroll
            for (int l = tid * 4; l < GBK * GBN; l += 128 * 4) {
                int r = l >> 6, c = l & 63;
                float4 v = *(const float4*)(Bb + (long long)(k0 + r) * N + bn0 + c);
                Bs[r * BS_LD + c + 0] = wmma::__float_to_tf32(v.x);
                Bs[r * BS_LD + c + 1] = wmma::__float_to_tf32(v.y);
                Bs[r * BS_LD + c + 2] = wmma::__float_to_tf32(v.z);
                Bs[r * BS_LD + c + 3] = wmma::__float_to_tf32(v.w);
            }
        } else {
            // B row-major N x K (we need B^T): Bs[k][n] = B[n][k]
#pragma unroll
            for (int l = tid * 4; l < GBK * GBN; l += 128 * 4) {
                int n = l >> 5, c = l & 31;
                float4 v = *(const float4*)(Bb + (long long)(bn0 + n) * K + k0 + c);
                Bs[(c + 0) * BS_LD + n] = wmma::__float_to_tf32(v.x);
                Bs[(c + 1) * BS_LD + n] = wmma::__float_to_tf32(v.y);
                Bs[(c + 2) * BS_LD + n] = wmma::__float_to_tf32(v.z);
                Bs[(c + 3) * BS_LD + n] = wmma::__float_to_tf32(v.w);
            }
        }
        __syncthreads();
#pragma unroll
        for (int kk = 0; kk < GBK; kk += 8) {
            wmma::fragment<wmma::matrix_a, 16, 16, 8, wmma::precision::tf32, wmma::row_major> af[2];
            wmma::fragment<wmma::matrix_b, 16, 16, 8, wmma::precision::tf32, wmma::row_major> bf[2];
#pragma unroll
            for (int i = 0; i < 2; i++)
                wmma::load_matrix_sync(af[i], As + (wr * 32 + i * 16) * AS_LD + kk, AS_LD);
#pragma unroll
            for (int j = 0; j < 2; j++)
                wmma::load_matrix_sync(bf[j], Bs + kk * BS_LD + wc * 32 + j * 16, BS_LD);
#pragma unroll
            for (int i = 0; i < 2; i++)
#pragma unroll
                for (int j = 0; j < 2; j++)
                    wmma::mma_sync(acc[i][j], af[i], bf[j], acc[i][j]);
        }
        __syncthreads();
    }

    // stage C through shared (reuses As/Bs space) for flexible scatter epilogue
    float* Cs = sbuf;  // 64 x 68 = 4352 <= 4480
#pragma unroll
    for (int i = 0; i < 2; i++)
#pragma unroll
        for (int j = 0; j < 2; j++)
            wmma::store_matrix_sync(Cs + (wr * 32 + i * 16) * CS_LD + wc * 32 + j * 16,
                                    acc[i][j], CS_LD, wmma::mem_row_major);
    __syncthreads();

    for (int l = tid; l < GBM * GBN; l += 128) {
        int i = l >> 6, j = l & 63;
        int m = bm0 + i, n = bn0 + j;
        float v = Cs[i * CS_LD + j] * alpha;
        if (bias) v += bias[n];
        if (doRelu) v = fmaxf(v, 0.0f);
        long long oidx;
        if (mode == MODE_PLAIN) {
            oidx = (long long)bz * cBatch + (long long)m * N + n;
        } else if (mode == MODE_HEADSPLIT) {
            // rows m in [0,16384): b = m/512, l = m%512 ; cols n in [0,1024): h = n/256, d = n%256
            int b = m >> 9, lr = m & 511;
            int h = n >> 8, d = n & 255;
            oidx = (((long long)(b * HH + h) * LL + lr) << 8) + d;
        } else {
            // MODE_MERGE: bz in [0,128): b = bz/4, h = bz%4 ; rows m = q, N = 256
            int b = bz >> 2, h = bz & 3;
            oidx = ((long long)(b * LL + m)) * HD + h * DD + n;
        }
        C[oidx] = v;
    }
}

// ---------------- causal + pad softmax (in-place on S) ----------------
__global__ void __launch_bounds__(128)
softmax_kernel(float* __restrict__ S) {
    int row = blockIdx.x;           // bh*512 + q
    int q = row & (LL - 1);
    int bh = row >> 9;
    int b = bh >> 2;
    float* srow = S + (size_t)row * LL;
    int tid = threadIdx.x;
    __shared__ float red[128];

    if (g_pad[(b << 9) + q]) {
        const float u = 1.0f / (float)LL;   // softmax of a constant row: exact
        for (int k = tid; k < LL; k += 128) srow[k] = u;
        return;
    }
    int valid = q + 1;
    float vals[4];
    float mx = -INFINITY;
#pragma unroll
    for (int t = 0; t < 4; t++) {
        int k = tid + t * 128;
        vals[t] = (k < valid) ? srow[k] : -INFINITY;
        mx = fmaxf(mx, vals[t]);
    }
    red[tid] = mx;
    __syncthreads();
    for (int s = 64; s > 0; s >>= 1) {
        if (tid < s) red[tid] = fmaxf(red[tid], red[tid + s]);
        __syncthreads();
    }
    mx = red[0];
    __syncthreads();
    float sum = 0.0f;
#pragma unroll
    for (int t = 0; t < 4; t++) {
        int k = tid + t * 128;
        vals[t] = (k < valid) ? expf(vals[t] - mx) : 0.0f;
        sum += vals[t];
    }
    red[tid] = sum;
    __syncthreads();
    for (int s = 64; s > 0; s >>= 1) {
        if (tid < s) red[tid] += red[tid + s];
        __syncthreads();
    }
    float inv = 1.0f / red[0];
#pragma unroll
    for (int t = 0; t < 4; t++) srow[tid + t * 128] = vals[t] * inv;
}

// ---------------- residual + layernorm (row = 256 elems, 1 thread each) ----------------
__global__ void __launch_bounds__(256)
ln_residual_kernel(const float* __restrict__ Ain, const float* __restrict__ Bin,
                   const float* __restrict__ gamma, const float* __restrict__ beta,
                   float* __restrict__ out) {
    int row = blockIdx.x;
    int tid = threadIdx.x;
    long long base = (long long)row * DD + tid;
    float x = Ain[base] + Bin[base];
    __shared__ float red[256];
    red[tid] = x;
    __syncthreads();
    for (int s = 128; s > 0; s >>= 1) {
        if (tid < s) red[tid] += red[tid + s];
        __syncthreads();
    }
    float mu = red[0] * (1.0f / DD);
    __syncthreads();
    float d = x - mu;
    red[tid] = d * d;
    __syncthreads();
    for (int s = 128; s > 0; s >>= 1) {
        if (tid < s) red[tid] += red[tid + s];
        __syncthreads();
    }
    float var = red[0] * (1.0f / DD);
    out[base] = d * rsqrtf(var + 1e-5f) * gamma[tid] + beta[tid];
}

// ---------------- host orchestration ----------------
extern "C" void kernel_launch(void* const* d_in, const int* in_sizes, int n_in,
                              void* d_out, int out_size) {
    (void)in_sizes; (void)n_in; (void)out_size;
    const float* Q    = (const float*)d_in[0];
    const float* K    = (const float*)d_in[1];
    const float* V    = (const float*)d_in[2];
    const void*  mask = d_in[3];
    const float* pe   = (const float*)d_in[4];
    const float* W_q  = (const float*)d_in[5];
    const float* W_k  = (const float*)d_in[6];
    const float* W_v  = (const float*)d_in[7];
    const float* W_o  = (const float*)d_in[8];
    const float* w1   = (const float*)d_in[9];
    const float* b1   = (const float*)d_in[10];
    const float* w2   = (const float*)d_in[11];
    const float* b2   = (const float*)d_in[12];
    const float* gamma = (const float*)d_in[13];
    const float* beta  = (const float*)d_in[14];
    float* out = (float*)d_out;

    void *pQp, *pKp, *pVp, *pQh, *pKh, *pVh, *pS, *pVm, *pT1, *pX, *pY, *pZ;
    cudaGetSymbolAddress(&pQp, g_Qp);
    cudaGetSymbolAddress(&pKp, g_Kp);
    cudaGetSymbolAddress(&pVp, g_Vp);
    cudaGetSymbolAddress(&pQh, g_Qh);
    cudaGetSymbolAddress(&pKh, g_Kh);
    cudaGetSymbolAddress(&pVh, g_Vh);
    cudaGetSymbolAddress(&pS, g_S);
    cudaGetSymbolAddress(&pVm, g_Vm);
    cudaGetSymbolAddress(&pT1, g_T1);
    cudaGetSymbolAddress(&pX, g_X);
    cudaGetSymbolAddress(&pY, g_Y);
    cudaGetSymbolAddress(&pZ, g_Z);

    // 1) mask decode
    detect_mask_kernel<<<1, 256>>>((const unsigned char*)mask);
    decode_mask_kernel<<<(NTOK + 255) / 256, 256>>>(mask);

    // 2) add positional encoding
    int etotal = NTOK * DD;
    int eblk = (etotal + 255) / 256;
    add_pe_kernel<<<eblk, 256>>>(Q, pe, (float*)pQp);
    add_pe_kernel<<<eblk, 256>>>(K, pe, (float*)pKp);
    add_pe_kernel<<<eblk, 256>>>(V, pe, (float*)pVp);

    // 3) QKV projections -> head-split layout (B*H, L, D)
    {
        dim3 grid(HD / GBN, NTOK / GBM, 1);
        gemm_tf32<false><<<grid, 128>>>((float*)pQp, W_q, (float*)pQh, NTOK, HD, DD,
                                        0, 0, 0, MODE_HEADSPLIT, nullptr, 1.0f, 0);
        gemm_tf32<false><<<grid, 128>>>((float*)pKp, W_k, (float*)pKh, NTOK, HD, DD,
                                        0, 0, 0, MODE_HEADSPLIT, nullptr, 1.0f, 0);
        gemm_tf32<false><<<grid, 128>>>((float*)pVp, W_v, (float*)pVh, NTOK, HD, DD,
                                        0, 0, 0, MODE_HEADSPLIT, nullptr, 1.0f, 0);
    }

    // 4) scores = Qh @ Kh^T / scale  (batched over B*H)
    {
        float alpha = (float)(1.0 / (16.0 + 1e-6));  // 1/(sqrt(256)+1e-6)
        dim3 grid(LL / GBN, LL / GBM, BH);
        gemm_tf32<true><<<grid, 128>>>((float*)pQh, (float*)pKh, (float*)pS, LL, LL, DD,
                                       (long long)LL * DD, (long long)LL * DD,
                                       (long long)LL * LL, MODE_PLAIN, nullptr, alpha, 0);
    }

    // 5) masked softmax (in-place)
    softmax_kernel<<<BH * LL, 128>>>((float*)pS);

    // 6) Vatt = att @ Vh -> merged (B, L, H*D)
    {
        dim3 grid(DD / GBN, LL / GBM, BH);
        gemm_tf32<false><<<grid, 128>>>((float*)pS, (float*)pVh, (float*)pVm, LL, DD, LL,
                                        (long long)LL * LL, (long long)LL * DD,
                                        0, MODE_MERGE, nullptr, 1.0f, 0);
    }

    // 7) output projection: T1 = Vm @ W_o
    {
        dim3 grid(DD / GBN, NTOK / GBM, 1);
        gemm_tf32<false><<<grid, 128>>>((float*)pVm, W_o, (float*)pT1, NTOK, DD, HD,
                                        0, 0, 0, MODE_PLAIN, nullptr, 1.0f, 0);
    }

    // 8) X = LN(Qp + T1)
    ln_residual_kernel<<<NTOK, 256>>>((float*)pQp, (float*)pT1, gamma, beta, (float*)pX);

    // 9) FFN: Y = relu(X @ w1^T + b1); Z = Y @ w2^T + b2
    {
        dim3 grid(DD / GBN, NTOK / GBM, 1);
        gemm_tf32<true><<<grid, 128>>>((float*)pX, w1, (float*)pY, NTOK, DD, DD,
                                       0, 0, 0, MODE_PLAIN, b1, 1.0f, 1);
        gemm_tf32<true><<<grid, 128>>>((float*)pY, w2, (float*)pZ, NTOK, DD, DD,
                                       0, 0, 0, MODE_PLAIN, b2, 1.0f, 0);
    }

    // 10) out = LN(Z + X)
    ln_residual_kernel<<<NTOK, 256>>>((float*)pZ, (float*)pX, gamma, beta, out);
}